// round 5
// baseline (speedup 1.0000x reference)
#include <cuda_runtime.h>

// ---------------------------------------------------------------------------
// out[i, j] = f(j-1) - f(j),  f(j) = relu(1 - relu(x_full[j+1] - x) /
//                                         (x_full[j+1] - x_full[j] + 1e-9))
// sentinels f(-1)=1, f(n_full-1)=0.  out == 0 outside a <=8-column window
// [k-2, k+5] around x's interval k.  Fully fused: one warp per row streams
// the row as STG.128 zeros with exact values in the window.  One kernel,
// one write of every output byte.
// ---------------------------------------------------------------------------

__device__ __forceinline__ float evalf_s(const float* __restrict__ sxf,
                                         int j, int n_full, float x) {
    if (j < 0) return 1.0f;
    if (j >= n_full - 1) return 0.0f;
    float xa = sxf[j];
    float xb = sxf[j + 1];
    float t  = fmaxf(0.f, xb - x);
    return fmaxf(0.f, 1.0f - t / (xb - xa + 1e-9f));
}

__device__ __forceinline__ float value_s(const float* __restrict__ sxf,
                                         int c, int n_full, float x) {
    return evalf_s(sxf, c - 1, n_full, x) - evalf_s(sxf, c, n_full, x);
}

__global__ void fused_kernel(const float* __restrict__ x_eval,
                             const float* __restrict__ x_full,
                             float* __restrict__ out,
                             int n_points, int n_full) {
    extern __shared__ float sxf[];   // n_full floats (8.2 KB @ 2049)
    for (int m = threadIdx.x; m < n_full; m += blockDim.x)
        sxf[m] = x_full[m];
    __syncthreads();

    int gwarp = (blockIdx.x * blockDim.x + threadIdx.x) >> 5;
    int lane  = threadIdx.x & 31;
    if (gwarp >= n_points) return;
    int r = gwarp;
    float x = __ldg(x_eval + r);     // warp-uniform broadcast

    // upper_bound in smem (all lanes redundant -> broadcast, no conflicts)
    int lo = 0, hi = n_full;
    while (lo < hi) {
        int mid = (lo + hi) >> 1;
        if (sxf[mid] <= x) lo = mid + 1;
        else hi = mid;
    }
    int k = lo - 1;
    k = (k < 0) ? 0 : k;
    if (k > n_full - 2) k = n_full - 2;
    int j0 = (k - 2 < 0) ? 0 : (k - 2);
    int j1 = (k + 5 > n_full - 1) ? (n_full - 1) : (k + 5);

    int base = r * n_full;                 // < 2^31 here
    int mis  = base & 3;
    int head = (4 - mis) & 3;              // scalar elems to reach 16B align
    if (head > n_full) head = n_full;

    // head scalars (<=3): always exact formula (cheap)
    if (lane < head)
        out[base + lane] = value_s(sxf, lane, n_full, x);

    int n_rem = n_full - head;
    int n4    = n_rem >> 2;
    int tail  = n_rem & 3;
    float4* o4 = reinterpret_cast<float4*>(out + base + head);

    const float4 z = make_float4(0.f, 0.f, 0.f, 0.f);
    #pragma unroll 4
    for (int t = lane; t < n4; t += 32) {
        int c = head + (t << 2);           // first column of this chunk
        float4 v;
        if (c + 3 < j0 || c > j1) {
            v = z;                          // common path: pure zero
        } else {
            v.x = value_s(sxf, c,     n_full, x);
            v.y = value_s(sxf, c + 1, n_full, x);
            v.z = value_s(sxf, c + 2, n_full, x);
            v.w = value_s(sxf, c + 3, n_full, x);
        }
        __stcs(o4 + t, v);                  // streaming STG.128
    }

    // tail scalars (<=3)
    if (lane < tail) {
        int c = head + (n4 << 2) + lane;
        out[base + c] = value_s(sxf, c, n_full, x);
    }
}

extern "C" void kernel_launch(void* const* d_in, const int* in_sizes, int n_in,
                              void* d_out, int out_size) {
    const float* x_eval = (const float*)d_in[0];  // (n_points, 1) float32
    const float* x_full = (const float*)d_in[1];  // (n_full,)    float32 sorted
    float* out = (float*)d_out;                   // (n_points, n_full) float32

    int n_points = in_sizes[0];
    int n_full   = in_sizes[1];

    int threads = 256;                            // 8 warps = 8 rows / block
    int warps_per_block = threads / 32;
    int blocks = (n_points + warps_per_block - 1) / warps_per_block;
    size_t smem = (size_t)n_full * sizeof(float);

    fused_kernel<<<blocks, threads, smem>>>(x_eval, x_full, out,
                                            n_points, n_full);
}

// round 6
// speedup vs baseline: 1.0495x; 1.0495x over previous
#include <cuda_runtime.h>

// ---------------------------------------------------------------------------
// out[i, j] = f(j-1) - f(j),  f(j) = relu(1 - relu(x_full[j+1] - x) /
//                                         (x_full[j+1] - x_full[j] + 1e-9))
// sentinels f(-1)=1, f(n_full-1)=0.  out == 0 outside [j0, j1] = [k-2, k+5]
// around x's interval k.  One warp per row; the row is split into
// zero-span / window-span / zero-span so the hot store loops carry ZERO
// per-iteration window logic (pure STG.128 stream).
// ---------------------------------------------------------------------------

__device__ __forceinline__ float evalf_s(const float* __restrict__ sxf,
                                         int j, int n_full, float x) {
    if (j < 0) return 1.0f;
    if (j >= n_full - 1) return 0.0f;
    float xa = sxf[j];
    float xb = sxf[j + 1];
    float t  = fmaxf(0.f, xb - x);
    return fmaxf(0.f, 1.0f - t / (xb - xa + 1e-9f));
}

__device__ __forceinline__ float value_s(const float* __restrict__ sxf,
                                         int c, int n_full, float x) {
    return evalf_s(sxf, c - 1, n_full, x) - evalf_s(sxf, c, n_full, x);
}

__global__ void fused_kernel(const float* __restrict__ x_eval,
                             const float* __restrict__ x_full,
                             float* __restrict__ out,
                             int n_points, int n_full) {
    extern __shared__ float sxf[];   // n_full floats (8.2 KB @ 2049)
    for (int m = threadIdx.x; m < n_full; m += blockDim.x)
        sxf[m] = x_full[m];
    __syncthreads();

    int gwarp = (blockIdx.x * blockDim.x + threadIdx.x) >> 5;
    int lane  = threadIdx.x & 31;
    if (gwarp >= n_points) return;
    float x = __ldg(x_eval + gwarp);           // warp-uniform

    // upper_bound in smem (redundant lanes -> broadcast reads)
    int lo = 0, hi = n_full;
    while (lo < hi) {
        int mid = (lo + hi) >> 1;
        if (sxf[mid] <= x) lo = mid + 1;
        else hi = mid;
    }
    int k = lo - 1;
    k = (k < 0) ? 0 : k;
    if (k > n_full - 2) k = n_full - 2;
    int j0 = (k - 2 < 0) ? 0 : (k - 2);
    int j1 = (k + 5 > n_full - 1) ? (n_full - 1) : (k + 5);

    int base = gwarp * n_full;                 // < 2^31
    int head = (-base) & 3;                    // scalars to 16B alignment
    if (head > n_full) head = n_full;

    if (lane < head)                           // head scalars: exact formula
        out[base + lane] = value_s(sxf, lane, n_full, x);

    int n_rem = n_full - head;
    int n4    = n_rem >> 2;
    int tail  = n_rem & 3;
    float4* o4 = reinterpret_cast<float4*>(out + base + head);

    // float4-chunk span touching the window (warp-uniform, <=3 chunks)
    int a    = j0 - head;
    int w_lo = (a <= 0) ? 0 : (a >> 2);
    int w_hi = (j1 - head) >> 2;
    if (w_hi > n4 - 1) w_hi = n4 - 1;
    if (w_hi < w_lo)   w_hi = w_lo;

    const float4 z = make_float4(0.f, 0.f, 0.f, 0.f);

    // zero span before window: branch-free pure store stream
    #pragma unroll 4
    for (int t = lane; t < w_lo; t += 32)
        __stcs(o4 + t, z);

    // zero span after window
    #pragma unroll 4
    for (int t = w_hi + 1 + lane; t < n4; t += 32)
        __stcs(o4 + t, z);

    // window chunks: one per lane, exact formula for all 4 elements
    int wc = w_lo + lane;
    if (wc <= w_hi) {
        int c = head + (wc << 2);
        float4 v;
        v.x = value_s(sxf, c,     n_full, x);
        v.y = value_s(sxf, c + 1, n_full, x);
        v.z = value_s(sxf, c + 2, n_full, x);
        v.w = value_s(sxf, c + 3, n_full, x);
        __stcs(o4 + wc, v);
    }

    // tail scalars (<=3): exact formula
    if (lane < tail) {
        int c = head + (n4 << 2) + lane;
        out[base + c] = value_s(sxf, c, n_full, x);
    }
}

extern "C" void kernel_launch(void* const* d_in, const int* in_sizes, int n_in,
                              void* d_out, int out_size) {
    const float* x_eval = (const float*)d_in[0];  // (n_points, 1) float32
    const float* x_full = (const float*)d_in[1];  // (n_full,)    float32 sorted
    float* out = (float*)d_out;                   // (n_points, n_full) float32

    int n_points = in_sizes[0];
    int n_full   = in_sizes[1];

    int threads = 256;                            // 8 rows per block
    int warps_per_block = threads / 32;
    int blocks = (n_points + warps_per_block - 1) / warps_per_block;
    size_t smem = (size_t)n_full * sizeof(float);

    fused_kernel<<<blocks, threads, smem>>>(x_eval, x_full, out,
                                            n_points, n_full);
}